// round 3
// baseline (speedup 1.0000x reference)
#include <cuda_runtime.h>

#define SEQ 4096
#define HID 1024
#define NLAYERS 4

// ---------------- device scratch (static, allowed) ----------------
__device__ float g_Zu[SEQ * HID];
__device__ float g_Zr[SEQ * HID];
__device__ float g_Zc[SEQ * HID];
__device__ float g_H[NLAYERS][SEQ * HID];   // one sentinel-clean buffer per layer scan
__device__ float g_zero[HID];               // stays zero forever (never written)

// fill all 4 H buffers with the sentinel (-1.0f); real h values are strictly in (0,1)
__global__ void poison_kernel() {
    float4* p = (float4*)g_H;
    const size_t n4 = (size_t)NLAYERS * SEQ * HID / 4;
    const float4 s = make_float4(-1.f, -1.f, -1.f, -1.f);
    for (size_t i = blockIdx.x * (size_t)blockDim.x + threadIdx.x; i < n4;
         i += (size_t)gridDim.x * blockDim.x)
        p[i] = s;
}

// L2-coherent ld/st (bypass L1 so cross-SM dataflow is coherent)
__device__ __forceinline__ float4 ldcg4(const float* p) {
    float4 v;
    asm volatile("ld.global.cg.v4.f32 {%0,%1,%2,%3},[%4];"
                 : "=f"(v.x), "=f"(v.y), "=f"(v.z), "=f"(v.w) : "l"(p) : "memory");
    return v;
}
__device__ __forceinline__ void stcg(float* p, float v) {
    asm volatile("st.global.cg.f32 [%0],%1;" :: "l"(p), "f"(v) : "memory");
}

// ---------------- fp32 SGEMM batch: C[z] = A[z] @ B[z]^T, shapes [4096,1024]x[1024,1024]
// 128x128 tile, K-tile 8, 256 threads, 8x8 microtile. blockIdx.z selects the GEMM.
struct GemmJob { const float* A; const float* B; float* C; };
__global__ __launch_bounds__(256) void sgemm_nt_batch(GemmJob j0, GemmJob j1, GemmJob j2) {
    const GemmJob job = (blockIdx.z == 0) ? j0 : (blockIdx.z == 1) ? j1 : j2;
    const float* __restrict__ A = job.A;
    const float* __restrict__ B = job.B;
    float* __restrict__ C = job.C;
    const int K = HID, N = HID;
    __shared__ float As[8][128];
    __shared__ float Bs[8][128];
    const int tid = threadIdx.x;
    const int m0 = blockIdx.y * 128;
    const int n0 = blockIdx.x * 128;
    const int tx = tid & 15;
    const int ty = tid >> 4;
    const int lrow = tid >> 1;
    const int kp = (tid & 1) * 4;

    const float* Ap = A + (m0 + lrow) * K + kp;
    const float* Bp = B + (n0 + lrow) * K + kp;

    float acc[8][8];
#pragma unroll
    for (int i = 0; i < 8; i++)
#pragma unroll
        for (int j = 0; j < 8; j++) acc[i][j] = 0.f;

    for (int k0 = 0; k0 < K; k0 += 8) {
        float4 av = *(const float4*)(Ap + k0);
        float4 bv = *(const float4*)(Bp + k0);
        __syncthreads();
        As[kp + 0][lrow] = av.x; As[kp + 1][lrow] = av.y;
        As[kp + 2][lrow] = av.z; As[kp + 3][lrow] = av.w;
        Bs[kp + 0][lrow] = bv.x; Bs[kp + 1][lrow] = bv.y;
        Bs[kp + 2][lrow] = bv.z; Bs[kp + 3][lrow] = bv.w;
        __syncthreads();
#pragma unroll
        for (int kk = 0; kk < 8; kk++) {
            float a[8], b[8];
#pragma unroll
            for (int i = 0; i < 8; i++) a[i] = As[kk][ty * 8 + i];
#pragma unroll
            for (int j = 0; j < 8; j++) b[j] = Bs[kk][tx * 8 + j];
#pragma unroll
            for (int i = 0; i < 8; i++)
#pragma unroll
                for (int j = 0; j < 8; j++) acc[i][j] = fmaf(a[i], b[j], acc[i][j]);
        }
    }
#pragma unroll
    for (int i = 0; i < 8; i++) {
        float* Cp = C + (m0 + ty * 8 + i) * N + n0 + tx * 8;
#pragma unroll
        for (int j = 0; j < 8; j++) Cp[j] = acc[i][j];
    }
}

// ---------------- dataflow GRU layer scan (no barriers; throttled polling) ----
// 128 CTAs x 8 warps; warp w of CTA b owns output j = 8b+w, fully independent.
// h values double as ready flags: sentinel -1.0, real values in (0,1).
__global__ __launch_bounds__(256, 1) void gru_scan(
    const float* __restrict__ Wu, const float* __restrict__ Wr, const float* __restrict__ Wc,
    const float* __restrict__ Bu, const float* __restrict__ Br, const float* __restrict__ Bc,
    const float* __restrict__ Pu, const float* __restrict__ Pr, const float* __restrict__ Pc,
    float* __restrict__ Hout, float* __restrict__ out_final) {
    const int warp = threadIdx.x >> 5;
    const int lane = threadIdx.x & 31;
    const int j = (blockIdx.x << 3) + warp;

    // register-resident weight rows: k = 128*i + 4*lane + c
    float wu[32], wr[32], wc[32];
    const float* wub = Wu + j * HID;
    const float* wrb = Wr + j * HID;
    const float* wcb = Wc + j * HID;
#pragma unroll
    for (int i = 0; i < 8; i++) {
        const int k = i * 128 + lane * 4;
        float4 a = *(const float4*)(wub + k);
        float4 b = *(const float4*)(wrb + k);
        float4 c = *(const float4*)(wcb + k);
        wu[4 * i + 0] = a.x; wu[4 * i + 1] = a.y; wu[4 * i + 2] = a.z; wu[4 * i + 3] = a.w;
        wr[4 * i + 0] = b.x; wr[4 * i + 1] = b.y; wr[4 * i + 2] = b.z; wr[4 * i + 3] = b.w;
        wc[4 * i + 0] = c.x; wc[4 * i + 1] = c.y; wc[4 * i + 2] = c.z; wc[4 * i + 3] = c.w;
    }
    const float bu = Bu[j], br = Br[j], bc = Bc[j];
    float hj = 0.f;
    const float* hsrc = g_zero;          // h(-1)=0 (0 > -0.5, passes poll immediately)

    for (int t = 0; t < SEQ; t++) {
        const float zu = __ldg(Pu + t * HID + j);
        const float zr = __ldg(Pr + t * HID + j);
        const float zc = __ldg(Pc + t * HID + j);

        // throttled dataflow poll: reload row until every value is real
        float4 h4v[8];
        for (;;) {
            bool ok = true;
#pragma unroll
            for (int i = 0; i < 8; i++) {
                h4v[i] = ldcg4(hsrc + i * 128 + lane * 4);
                ok &= (h4v[i].x > -0.5f) & (h4v[i].y > -0.5f) &
                      (h4v[i].z > -0.5f) & (h4v[i].w > -0.5f);
            }
            if (__all_sync(0xffffffffu, ok)) break;
            __nanosleep(100);            // cap spin traffic well below LTS ceiling
        }

        float au = 0.f, ar = 0.f, ac = 0.f;
#pragma unroll
        for (int i = 0; i < 8; i++) {
            au = fmaf(wu[4 * i + 0], h4v[i].x, au);
            ar = fmaf(wr[4 * i + 0], h4v[i].x, ar);
            ac = fmaf(wc[4 * i + 0], h4v[i].x, ac);
            au = fmaf(wu[4 * i + 1], h4v[i].y, au);
            ar = fmaf(wr[4 * i + 1], h4v[i].y, ar);
            ac = fmaf(wc[4 * i + 1], h4v[i].y, ac);
            au = fmaf(wu[4 * i + 2], h4v[i].z, au);
            ar = fmaf(wr[4 * i + 2], h4v[i].z, ar);
            ac = fmaf(wc[4 * i + 2], h4v[i].z, ac);
            au = fmaf(wu[4 * i + 3], h4v[i].w, au);
            ar = fmaf(wr[4 * i + 3], h4v[i].w, ar);
            ac = fmaf(wc[4 * i + 3], h4v[i].w, ac);
        }
#pragma unroll
        for (int off = 16; off > 0; off >>= 1) {
            au += __shfl_xor_sync(0xffffffffu, au, off);
            ar += __shfl_xor_sync(0xffffffffu, ar, off);
            ac += __shfl_xor_sync(0xffffffffu, ac, off);
        }
        const float u = 1.f / (1.f + __expf(-(au + zu + bu)));
        const float r = 1.f / (1.f + __expf(-(ar + zr + br)));
        const float c = 1.f / (1.f + __expf(-(zc + r * ac + bc)));
        const float hn = fmaf(u, hj - c, c);
        hj = hn;

        if (lane == 0) stcg(Hout + t * HID + j, hn);   // the value IS the flag
        hsrc = Hout + t * HID;
    }
    if (lane == 0) out_final[j] = hj;
}

// ---------------- launch ----------------
extern "C" void kernel_launch(void* const* d_in, const int* in_sizes, int n_in,
                              void* d_out, int out_size) {
    const float* x   = (const float*)d_in[0];
    const float* Uu  = (const float*)d_in[1];
    const float* Ur  = (const float*)d_in[2];
    const float* U   = (const float*)d_in[3];
    const float* Wu  = (const float*)d_in[4];
    const float* Wr  = (const float*)d_in[5];
    const float* W   = (const float*)d_in[6];
    const float* Bu  = (const float*)d_in[7];
    const float* Br  = (const float*)d_in[8];
    const float* B   = (const float*)d_in[9];
    const float* Uhr = (const float*)d_in[10];
    const float* Uh  = (const float*)d_in[11];
    float* out = (float*)d_out;

    float *Zu, *Zr, *Zc, *Hb;
    cudaGetSymbolAddress((void**)&Zu, g_Zu);
    cudaGetSymbolAddress((void**)&Zr, g_Zr);
    cudaGetSymbolAddress((void**)&Zc, g_Zc);
    cudaGetSymbolAddress((void**)&Hb, g_H);

    poison_kernel<<<1024, 256>>>();

    // layer 0 input projections: 3 GEMMs merged into one launch
    {
        dim3 gg(HID / 128, SEQ / 128, 3);
        GemmJob a{x, Uu, Zu}, b{x, Ur, Zr}, c{x, U, Zc};
        sgemm_nt_batch<<<gg, 256>>>(a, b, c);
    }
    gru_scan<<<128, 256>>>(Wu, Wr, W, Bu, Br, B, Zu, Zr, Zc, Hb, out);

    for (int l = 1; l < NLAYERS; l++) {
        const float* Hp = Hb + (size_t)(l - 1) * SEQ * HID;
        float*       Hn = Hb + (size_t)l * SEQ * HID;
        // shared = Uh[l-1] @ h_{l-1} (feeds BOTH update gate and candidate); Uhr separate
        dim3 gg(HID / 128, SEQ / 128, 2);
        GemmJob a{Hp, Uh  + (size_t)(l - 1) * HID * HID, Zu};
        GemmJob b{Hp, Uhr + (size_t)(l - 1) * HID * HID, Zr};
        sgemm_nt_batch<<<gg, 256>>>(a, b, a);
        gru_scan<<<128, 256>>>(Wu + (size_t)l * HID * HID,
                               Wr + (size_t)l * HID * HID,
                               W  + (size_t)l * HID * HID,
                               Bu + l * HID, Br + l * HID, B + l * HID,
                               Zu, Zr, Zu,   // Pc aliases Pu: shared term
                               Hn, out + l * HID);
    }
    (void)in_sizes; (void)n_in; (void)out_size;
}

// round 6
// speedup vs baseline: 9.9778x; 9.9778x over previous
#include <cuda_runtime.h>

#define SEQ 4096
#define HID 1024
#define NLAYERS 4
#define NCTA 128
#define NCTR 16              // distributed barrier counters
#define CTRSTRIDE 32         // ints between counters -> separate 128B lines

// ---------------- device scratch (static, allowed) ----------------
__device__ float g_Zu[SEQ * HID];
__device__ float g_Zr[SEQ * HID];
__device__ float g_Zc[SEQ * HID];
__device__ float g_H[NLAYERS][SEQ * HID];
__device__ int   g_ctr[NLAYERS][NCTR * CTRSTRIDE];

__global__ void reset_ctrs_kernel() {
    int i = blockIdx.x * blockDim.x + threadIdx.x;
    if (i < NLAYERS * NCTR * CTRSTRIDE) ((int*)g_ctr)[i] = 0;
}

// L2-coherent vector load (bypass L1 so cross-SM exchange is coherent)
__device__ __forceinline__ float4 ldcg4(const float* p) {
    float4 v;
    asm volatile("ld.global.cg.v4.f32 {%0,%1,%2,%3},[%4];"
                 : "=f"(v.x), "=f"(v.y), "=f"(v.z), "=f"(v.w) : "l"(p) : "memory");
    return v;
}
__device__ __forceinline__ void stcg(float* p, float v) {
    asm volatile("st.global.cg.f32 [%0],%1;" :: "l"(p), "f"(v) : "memory");
}

// packed fp32x2 helpers (FFMA2 — bit-identical fp32 math)
typedef unsigned long long ull;
__device__ __forceinline__ ull pack2(float lo, float hi) {
    ull r; asm("mov.b64 %0,{%1,%2};" : "=l"(r) : "f"(lo), "f"(hi)); return r;
}
__device__ __forceinline__ ull fma2(ull a, ull b, ull c) {
    ull d; asm("fma.rn.f32x2 %0,%1,%2,%3;" : "=l"(d) : "l"(a), "l"(b), "l"(c)); return d;
}
__device__ __forceinline__ float sum2(ull v) {
    float lo, hi; asm("mov.b64 {%0,%1},%2;" : "=f"(lo), "=f"(hi) : "l"(v));
    return lo + hi;
}

// ---------------- fp32 SGEMM batch: C[z] = A[z] @ B[z]^T ----------------
struct GemmJob { const float* A; const float* B; float* C; };
__global__ __launch_bounds__(256) void sgemm_nt_batch(GemmJob j0, GemmJob j1, GemmJob j2) {
    const GemmJob job = (blockIdx.z == 0) ? j0 : (blockIdx.z == 1) ? j1 : j2;
    const float* __restrict__ A = job.A;
    const float* __restrict__ B = job.B;
    float* __restrict__ C = job.C;
    const int K = HID, N = HID;
    __shared__ float As[8][128];
    __shared__ float Bs[8][128];
    const int tid = threadIdx.x;
    const int m0 = blockIdx.y * 128;
    const int n0 = blockIdx.x * 128;
    const int tx = tid & 15;
    const int ty = tid >> 4;
    const int lrow = tid >> 1;
    const int kp = (tid & 1) * 4;

    const float* Ap = A + (m0 + lrow) * K + kp;
    const float* Bp = B + (n0 + lrow) * K + kp;

    float acc[8][8];
#pragma unroll
    for (int i = 0; i < 8; i++)
#pragma unroll
        for (int j = 0; j < 8; j++) acc[i][j] = 0.f;

    for (int k0 = 0; k0 < K; k0 += 8) {
        float4 av = *(const float4*)(Ap + k0);
        float4 bv = *(const float4*)(Bp + k0);
        __syncthreads();
        As[kp + 0][lrow] = av.x; As[kp + 1][lrow] = av.y;
        As[kp + 2][lrow] = av.z; As[kp + 3][lrow] = av.w;
        Bs[kp + 0][lrow] = bv.x; Bs[kp + 1][lrow] = bv.y;
        Bs[kp + 2][lrow] = bv.z; Bs[kp + 3][lrow] = bv.w;
        __syncthreads();
#pragma unroll
        for (int kk = 0; kk < 8; kk++) {
            float a[8], b[8];
#pragma unroll
            for (int i = 0; i < 8; i++) a[i] = As[kk][ty * 8 + i];
#pragma unroll
            for (int j = 0; j < 8; j++) b[j] = Bs[kk][tx * 8 + j];
#pragma unroll
            for (int i = 0; i < 8; i++)
#pragma unroll
                for (int j = 0; j < 8; j++) acc[i][j] = fmaf(a[i], b[j], acc[i][j]);
        }
    }
#pragma unroll
    for (int i = 0; i < 8; i++) {
        float* Cp = C + (m0 + ty * 8 + i) * N + n0 + tx * 8;
#pragma unroll
        for (int j = 0; j < 8; j++) Cp[j] = acc[i][j];
    }
}

// ---------------- GRU layer scan: R1-proven sync, distributed + staged -----
// 128 CTAs x 8 warps; warp w of CTA b owns output j = 8b+w.
// Publish: st.cg h; threadfence(storer); syncthreads; thread0 atomicAdd on
// counter (bid & 15). Wait: lanes 0-15 of warp 0 scalar-volatile spin (one
// counter each, R1's exact loop), syncwarp, warp0 stages row to SMEM, bar.
__global__ __launch_bounds__(256, 1) void gru_scan(
    const float* __restrict__ Wu, const float* __restrict__ Wr, const float* __restrict__ Wc,
    const float* __restrict__ Bu, const float* __restrict__ Br, const float* __restrict__ Bc,
    const float* __restrict__ Pu, const float* __restrict__ Pr, const float* __restrict__ Pc,
    float* __restrict__ Hout, float* __restrict__ out_final, int* __restrict__ ctr) {
    __shared__ float sh[HID];
    const int warp = threadIdx.x >> 5;
    const int lane = threadIdx.x & 31;
    const int j = (blockIdx.x << 3) + warp;

    // register-resident packed weight rows: chunk i covers k = i*128 + lane*4 + {0..3}
    ull wu2[16], wr2[16], wc2[16];
    const float* wub = Wu + j * HID;
    const float* wrb = Wr + j * HID;
    const float* wcb = Wc + j * HID;
#pragma unroll
    for (int i = 0; i < 8; i++) {
        const int k = i * 128 + lane * 4;
        float4 a = *(const float4*)(wub + k);
        float4 b = *(const float4*)(wrb + k);
        float4 c = *(const float4*)(wcb + k);
        wu2[2 * i] = pack2(a.x, a.y); wu2[2 * i + 1] = pack2(a.z, a.w);
        wr2[2 * i] = pack2(b.x, b.y); wr2[2 * i + 1] = pack2(b.z, b.w);
        wc2[2 * i] = pack2(c.x, c.y); wc2[2 * i + 1] = pack2(c.z, c.w);
    }
    const float bu = Bu[j], br = Br[j], bc = Bc[j];
    float hj = 0.f;
    volatile int* vctr = (volatile int*)(ctr + lane * CTRSTRIDE);  // lanes 0-15 use it

    for (int t = 0; t < SEQ; t++) {
        const float zu = __ldg(Pu + t * HID + j);
        const float zr = __ldg(Pr + t * HID + j);
        const float zc = __ldg(Pc + t * HID + j);

        if (warp == 0) {
            if (t > 0) {
                // wait: counter c must reach t * (NCTA/NCTR)
                if (lane < NCTR) {
                    const int tgt = t * (NCTA / NCTR);
                    while (*vctr < tgt) { }        // R1's proven scalar spin
                }
                __syncwarp();
                const float* hrow = Hout + (t - 1) * HID;
#pragma unroll
                for (int i = 0; i < 8; i++)
                    *(float4*)(sh + i * 128 + lane * 4) = ldcg4(hrow + i * 128 + lane * 4);
            } else {
#pragma unroll
                for (int i = 0; i < 8; i++)
                    *(float4*)(sh + i * 128 + lane * 4) = make_float4(0.f, 0.f, 0.f, 0.f);
            }
        }
        __syncthreads();   // bar A: SMEM row ready

        ull au2 = 0, ar2 = 0, ac2 = 0;
#pragma unroll
        for (int i = 0; i < 8; i++) {
            float4 h4 = *(const float4*)(sh + i * 128 + lane * 4);
            const ull h01 = pack2(h4.x, h4.y);
            const ull h23 = pack2(h4.z, h4.w);
            au2 = fma2(wu2[2 * i], h01, au2);
            ar2 = fma2(wr2[2 * i], h01, ar2);
            ac2 = fma2(wc2[2 * i], h01, ac2);
            au2 = fma2(wu2[2 * i + 1], h23, au2);
            ar2 = fma2(wr2[2 * i + 1], h23, ar2);
            ac2 = fma2(wc2[2 * i + 1], h23, ac2);
        }
        float au = sum2(au2), ar = sum2(ar2), ac = sum2(ac2);
#pragma unroll
        for (int off = 16; off > 0; off >>= 1) {
            au += __shfl_xor_sync(0xffffffffu, au, off);
            ar += __shfl_xor_sync(0xffffffffu, ar, off);
            ac += __shfl_xor_sync(0xffffffffu, ac, off);
        }
        const float u = 1.f / (1.f + __expf(-(au + zu + bu)));
        const float r = 1.f / (1.f + __expf(-(ar + zr + br)));
        const float c = 1.f / (1.f + __expf(-(zc + r * ac + bc)));
        const float hn = fmaf(u, hj - c, c);
        hj = hn;

        if (lane == 0) {
            stcg(Hout + t * HID + j, hn);
            __threadfence();               // storer-side release (R1 pattern)
        }
        __syncthreads();   // bar B: stores + fences done CTA-wide
        if (threadIdx.x == 0)
            atomicAdd(ctr + (blockIdx.x & (NCTR - 1)) * CTRSTRIDE, 1);
    }
    if (lane == 0) out_final[j] = hj;
}

// ---------------- launch ----------------
extern "C" void kernel_launch(void* const* d_in, const int* in_sizes, int n_in,
                              void* d_out, int out_size) {
    const float* x   = (const float*)d_in[0];
    const float* Uu  = (const float*)d_in[1];
    const float* Ur  = (const float*)d_in[2];
    const float* U   = (const float*)d_in[3];
    const float* Wu  = (const float*)d_in[4];
    const float* Wr  = (const float*)d_in[5];
    const float* W   = (const float*)d_in[6];
    const float* Bu  = (const float*)d_in[7];
    const float* Br  = (const float*)d_in[8];
    const float* B   = (const float*)d_in[9];
    const float* Uhr = (const float*)d_in[10];
    const float* Uh  = (const float*)d_in[11];
    float* out = (float*)d_out;

    float *Zu, *Zr, *Zc, *Hb;
    int* ct;
    cudaGetSymbolAddress((void**)&Zu, g_Zu);
    cudaGetSymbolAddress((void**)&Zr, g_Zr);
    cudaGetSymbolAddress((void**)&Zc, g_Zc);
    cudaGetSymbolAddress((void**)&Hb, g_H);
    cudaGetSymbolAddress((void**)&ct, g_ctr);

    reset_ctrs_kernel<<<(NLAYERS * NCTR * CTRSTRIDE + 255) / 256, 256>>>();

    // layer 0 input projections: 3 GEMMs in one launch
    {
        dim3 gg(HID / 128, SEQ / 128, 3);
        GemmJob a{x, Uu, Zu}, b{x, Ur, Zr}, c{x, U, Zc};
        sgemm_nt_batch<<<gg, 256>>>(a, b, c);
    }
    gru_scan<<<NCTA, 256>>>(Wu, Wr, W, Bu, Br, B, Zu, Zr, Zc, Hb, out, ct);

    for (int l = 1; l < NLAYERS; l++) {
        const float* Hp = Hb + (size_t)(l - 1) * SEQ * HID;
        float*       Hn = Hb + (size_t)l * SEQ * HID;
        // shared = Uh[l-1] @ h_{l-1} (feeds BOTH update gate and candidate); Uhr separate
        dim3 gg(HID / 128, SEQ / 128, 2);
        GemmJob a{Hp, Uh  + (size_t)(l - 1) * HID * HID, Zu};
        GemmJob b{Hp, Uhr + (size_t)(l - 1) * HID * HID, Zr};
        sgemm_nt_batch<<<gg, 256>>>(a, b, a);
        gru_scan<<<NCTA, 256>>>(Wu + (size_t)l * HID * HID,
                                Wr + (size_t)l * HID * HID,
                                W  + (size_t)l * HID * HID,
                                Bu + l * HID, Br + l * HID, B + l * HID,
                                Zu, Zr, Zu,   // Pc aliases Pu: shared term
                                Hn, out + l * HID, ct + l * NCTR * CTRSTRIDE);
    }
    (void)in_sizes; (void)n_in; (void)out_size;
}

// round 7
// speedup vs baseline: 10.1063x; 1.0129x over previous
#include <cuda_runtime.h>

#define SEQ 4096
#define HID 1024
#define NLAYERS 4
#define NCTA 128
#define NCTR 16              // distributed barrier counters
#define CTRSTRIDE 32         // ints between counters -> separate 128B lines
#define ARR_PER_STEP 64      // arrivals per counter per step (8 CTAs x 8 warps)

// ---------------- device scratch (static, allowed) ----------------
__device__ float g_Zu[SEQ * HID];
__device__ float g_Zr[SEQ * HID];
__device__ float g_Zc[SEQ * HID];
__device__ float g_H[NLAYERS][SEQ * HID];
__device__ int   g_ctr[NLAYERS][NCTR * CTRSTRIDE];

__global__ void reset_ctrs_kernel() {
    int i = blockIdx.x * blockDim.x + threadIdx.x;
    if (i < NLAYERS * NCTR * CTRSTRIDE) ((int*)g_ctr)[i] = 0;
}

// L2-coherent vector load (bypass L1 so cross-SM exchange is coherent)
__device__ __forceinline__ float4 ldcg4(const float* p) {
    float4 v;
    asm volatile("ld.global.cg.v4.f32 {%0,%1,%2,%3},[%4];"
                 : "=f"(v.x), "=f"(v.y), "=f"(v.z), "=f"(v.w) : "l"(p) : "memory");
    return v;
}
__device__ __forceinline__ void stcg(float* p, float v) {
    asm volatile("st.global.cg.f32 [%0],%1;" :: "l"(p), "f"(v) : "memory");
}
// acquire load for the spin (orders subsequent row reads after observed release)
__device__ __forceinline__ int ldacq(const int* p) {
    int v;
    asm volatile("ld.acquire.gpu.global.s32 %0,[%1];" : "=r"(v) : "l"(p) : "memory");
    return v;
}
// release reduction publish: orders this thread's prior st.cg before the increment
__device__ __forceinline__ void red_release_add(int* p, int v) {
    asm volatile("red.release.gpu.global.add.s32 [%0],%1;" :: "l"(p), "r"(v) : "memory");
}

// packed fp32x2 helpers (FFMA2 — bit-identical fp32 math)
typedef unsigned long long ull;
__device__ __forceinline__ ull pack2(float lo, float hi) {
    ull r; asm("mov.b64 %0,{%1,%2};" : "=l"(r) : "f"(lo), "f"(hi)); return r;
}
__device__ __forceinline__ ull fma2(ull a, ull b, ull c) {
    ull d; asm("fma.rn.f32x2 %0,%1,%2,%3;" : "=l"(d) : "l"(a), "l"(b), "l"(c)); return d;
}
__device__ __forceinline__ float sum2(ull v) {
    float lo, hi; asm("mov.b64 {%0,%1},%2;" : "=f"(lo), "=f"(hi) : "l"(v));
    return lo + hi;
}

// ---------------- fp32 SGEMM batch: C[z] = A[z] @ B[z]^T ----------------
struct GemmJob { const float* A; const float* B; float* C; };
__global__ __launch_bounds__(256) void sgemm_nt_batch(GemmJob j0, GemmJob j1, GemmJob j2) {
    const GemmJob job = (blockIdx.z == 0) ? j0 : (blockIdx.z == 1) ? j1 : j2;
    const float* __restrict__ A = job.A;
    const float* __restrict__ B = job.B;
    float* __restrict__ C = job.C;
    const int K = HID, N = HID;
    __shared__ float As[8][128];
    __shared__ float Bs[8][128];
    const int tid = threadIdx.x;
    const int m0 = blockIdx.y * 128;
    const int n0 = blockIdx.x * 128;
    const int tx = tid & 15;
    const int ty = tid >> 4;
    const int lrow = tid >> 1;
    const int kp = (tid & 1) * 4;

    const float* Ap = A + (m0 + lrow) * K + kp;
    const float* Bp = B + (n0 + lrow) * K + kp;

    float acc[8][8];
#pragma unroll
    for (int i = 0; i < 8; i++)
#pragma unroll
        for (int j = 0; j < 8; j++) acc[i][j] = 0.f;

    for (int k0 = 0; k0 < K; k0 += 8) {
        float4 av = *(const float4*)(Ap + k0);
        float4 bv = *(const float4*)(Bp + k0);
        __syncthreads();
        As[kp + 0][lrow] = av.x; As[kp + 1][lrow] = av.y;
        As[kp + 2][lrow] = av.z; As[kp + 3][lrow] = av.w;
        Bs[kp + 0][lrow] = bv.x; Bs[kp + 1][lrow] = bv.y;
        Bs[kp + 2][lrow] = bv.z; Bs[kp + 3][lrow] = bv.w;
        __syncthreads();
#pragma unroll
        for (int kk = 0; kk < 8; kk++) {
            float a[8], b[8];
#pragma unroll
            for (int i = 0; i < 8; i++) a[i] = As[kk][ty * 8 + i];
#pragma unroll
            for (int j = 0; j < 8; j++) b[j] = Bs[kk][tx * 8 + j];
#pragma unroll
            for (int i = 0; i < 8; i++)
#pragma unroll
                for (int j = 0; j < 8; j++) acc[i][j] = fmaf(a[i], b[j], acc[i][j]);
        }
    }
#pragma unroll
    for (int i = 0; i < 8; i++) {
        float* Cp = C + (m0 + ty * 8 + i) * N + n0 + tx * 8;
#pragma unroll
        for (int j = 0; j < 8; j++) Cp[j] = acc[i][j];
    }
}

// ---------------- GRU layer scan: release-publish / acquire-poll -----------
// 128 CTAs x 8 warps; warp w of CTA b owns output j = 8b+w.
// Per step: warp0 acquire-polls 16 counters (>= 64*t), stages row t-1 into
// ping-pong SMEM; ONE __syncthreads; all warps compute; each warp's lane0
// does st.cg(h) then red.release on counter (bid&15). No membar, no 2nd bar.
__global__ __launch_bounds__(256, 1) void gru_scan(
    const float* __restrict__ Wu, const float* __restrict__ Wr, const float* __restrict__ Wc,
    const float* __restrict__ Bu, const float* __restrict__ Br, const float* __restrict__ Bc,
    const float* __restrict__ Pu, const float* __restrict__ Pr, const float* __restrict__ Pc,
    float* __restrict__ Hout, float* __restrict__ out_final, int* __restrict__ ctr) {
    __shared__ float sh[2][HID];
    const int warp = threadIdx.x >> 5;
    const int lane = threadIdx.x & 31;
    const int j = (blockIdx.x << 3) + warp;
    int* const myctr = ctr + (blockIdx.x & (NCTR - 1)) * CTRSTRIDE;

    // register-resident packed weight rows: chunk i covers k = i*128 + lane*4 + {0..3}
    ull wu2[16], wr2[16], wc2[16];
    const float* wub = Wu + j * HID;
    const float* wrb = Wr + j * HID;
    const float* wcb = Wc + j * HID;
#pragma unroll
    for (int i = 0; i < 8; i++) {
        const int k = i * 128 + lane * 4;
        float4 a = *(const float4*)(wub + k);
        float4 b = *(const float4*)(wrb + k);
        float4 c = *(const float4*)(wcb + k);
        wu2[2 * i] = pack2(a.x, a.y); wu2[2 * i + 1] = pack2(a.z, a.w);
        wr2[2 * i] = pack2(b.x, b.y); wr2[2 * i + 1] = pack2(b.z, b.w);
        wc2[2 * i] = pack2(c.x, c.y); wc2[2 * i + 1] = pack2(c.z, c.w);
    }
    const float bu = Bu[j], br = Br[j], bc = Bc[j];
    float hj = 0.f;
    const int* const spin_ctr = ctr + lane * CTRSTRIDE;  // lanes 0-15 use it

    for (int t = 0; t < SEQ; t++) {
        const float zu = __ldg(Pu + t * HID + j);
        const float zr = __ldg(Pr + t * HID + j);
        const float zc = __ldg(Pc + t * HID + j);
        float* shrow = sh[t & 1];

        if (warp == 0) {
            if (t > 0) {
                if (lane < NCTR) {
                    const int tgt = t * ARR_PER_STEP;
                    while (ldacq(spin_ctr) < tgt) { }
                }
                __syncwarp();
                const float* hrow = Hout + (t - 1) * HID;
#pragma unroll
                for (int i = 0; i < 8; i++)
                    *(float4*)(shrow + i * 128 + lane * 4) = ldcg4(hrow + i * 128 + lane * 4);
            } else {
#pragma unroll
                for (int i = 0; i < 8; i++)
                    *(float4*)(shrow + i * 128 + lane * 4) = make_float4(0.f, 0.f, 0.f, 0.f);
            }
        }
        __syncthreads();   // single barrier per step: SMEM row ready / prev reads done

        ull au2 = 0, ar2 = 0, ac2 = 0;
#pragma unroll
        for (int i = 0; i < 8; i++) {
            float4 h4 = *(const float4*)(shrow + i * 128 + lane * 4);
            const ull h01 = pack2(h4.x, h4.y);
            const ull h23 = pack2(h4.z, h4.w);
            au2 = fma2(wu2[2 * i], h01, au2);
            ar2 = fma2(wr2[2 * i], h01, ar2);
            ac2 = fma2(wc2[2 * i], h01, ac2);
            au2 = fma2(wu2[2 * i + 1], h23, au2);
            ar2 = fma2(wr2[2 * i + 1], h23, ar2);
            ac2 = fma2(wc2[2 * i + 1], h23, ac2);
        }
        float au = sum2(au2), ar = sum2(ar2), ac = sum2(ac2);
#pragma unroll
        for (int off = 16; off > 0; off >>= 1) {
            au += __shfl_xor_sync(0xffffffffu, au, off);
            ar += __shfl_xor_sync(0xffffffffu, ar, off);
            ac += __shfl_xor_sync(0xffffffffu, ac, off);
        }
        const float u = 1.f / (1.f + __expf(-(au + zu + bu)));
        const float r = 1.f / (1.f + __expf(-(ar + zr + br)));
        const float c = 1.f / (1.f + __expf(-(zc + r * ac + bc)));
        const float hn = fmaf(u, hj - c, c);
        hj = hn;

        if (lane == 0) {
            stcg(Hout + t * HID + j, hn);     // data
            red_release_add(myctr, 1);        // release-publish (orders the store)
        }
    }
    if (lane == 0) out_final[j] = hj;
}

// ---------------- launch ----------------
extern "C" void kernel_launch(void* const* d_in, const int* in_sizes, int n_in,
                              void* d_out, int out_size) {
    const float* x   = (const float*)d_in[0];
    const float* Uu  = (const float*)d_in[1];
    const float* Ur  = (const float*)d_in[2];
    const float* U   = (const float*)d_in[3];
    const float* Wu  = (const float*)d_in[4];
    const float* Wr  = (const float*)d_in[5];
    const float* W   = (const float*)d_in[6];
    const float* Bu  = (const float*)d_in[7];
    const float* Br  = (const float*)d_in[8];
    const float* B   = (const float*)d_in[9];
    const float* Uhr = (const float*)d_in[10];
    const float* Uh  = (const float*)d_in[11];
    float* out = (float*)d_out;

    float *Zu, *Zr, *Zc, *Hb;
    int* ct;
    cudaGetSymbolAddress((void**)&Zu, g_Zu);
    cudaGetSymbolAddress((void**)&Zr, g_Zr);
    cudaGetSymbolAddress((void**)&Zc, g_Zc);
    cudaGetSymbolAddress((void**)&Hb, g_H);
    cudaGetSymbolAddress((void**)&ct, g_ctr);

    reset_ctrs_kernel<<<(NLAYERS * NCTR * CTRSTRIDE + 255) / 256, 256>>>();

    // layer 0 input projections: 3 GEMMs in one launch
    {
        dim3 gg(HID / 128, SEQ / 128, 3);
        GemmJob a{x, Uu, Zu}, b{x, Ur, Zr}, c{x, U, Zc};
        sgemm_nt_batch<<<gg, 256>>>(a, b, c);
    }
    gru_scan<<<NCTA, 256>>>(Wu, Wr, W, Bu, Br, B, Zu, Zr, Zc, Hb, out, ct);

    for (int l = 1; l < NLAYERS; l++) {
        const float* Hp = Hb + (size_t)(l - 1) * SEQ * HID;
        float*       Hn = Hb + (size_t)l * SEQ * HID;
        // shared = Uh[l-1] @ h_{l-1} (feeds BOTH update gate and candidate); Uhr separate
        dim3 gg(HID / 128, SEQ / 128, 2);
        GemmJob a{Hp, Uh  + (size_t)(l - 1) * HID * HID, Zu};
        GemmJob b{Hp, Uhr + (size_t)(l - 1) * HID * HID, Zr};
        sgemm_nt_batch<<<gg, 256>>>(a, b, a);
        gru_scan<<<NCTA, 256>>>(Wu + (size_t)l * HID * HID,
                                Wr + (size_t)l * HID * HID,
                                W  + (size_t)l * HID * HID,
                                Bu + l * HID, Br + l * HID, B + l * HID,
                                Zu, Zr, Zu,   // Pc aliases Pu: shared term
                                Hn, out + l * HID, ct + l * NCTR * CTRSTRIDE);
    }
    (void)in_sizes; (void)n_in; (void)out_size;
}